// round 6
// baseline (speedup 1.0000x reference)
#include <cuda_runtime.h>

#define T_STEPS 10
#define B_SZ    32
#define CIN     3
#define COUT    64
#define SPAT    4096            // 64*64
#define N_THR   (T_STEPS * COUT)
#define DECAY   0.2f
#define INH     1.625f

// Scratch: conv results for all timesteps, layout (t,b,c,h,w).
__device__ float    g_i[T_STEPS * B_SZ * COUT * SPAT];   // 335.5 MB
__device__ unsigned g_thr_keys[N_THR];
__device__ float4   g_thrv[N_THR];   // {thr, INH*thr, 8*log2e/thr, 0}

// ---- packed f32x2 helpers (FFMA2 path; per-component IEEE rn) -------------
__device__ __forceinline__ unsigned long long pk2(float lo, float hi) {
    unsigned long long r;
    asm("mov.b64 %0, {%1,%2};" : "=l"(r) : "f"(lo), "f"(hi));
    return r;
}
__device__ __forceinline__ void upk2(unsigned long long v, float& lo, float& hi) {
    asm("mov.b64 {%0,%1}, %2;" : "=f"(lo), "=f"(hi) : "l"(v));
}
__device__ __forceinline__ unsigned long long fma2(unsigned long long a,
                                                   unsigned long long b,
                                                   unsigned long long c) {
    unsigned long long d;
    asm("fma.rn.f32x2 %0, %1, %2, %3;" : "=l"(d) : "l"(a), "l"(b), "l"(c));
    return d;
}
__device__ __forceinline__ unsigned long long add2(unsigned long long a,
                                                   unsigned long long b) {
    unsigned long long d;
    asm("add.rn.f32x2 %0, %1, %2;" : "=l"(d) : "l"(a), "l"(b));
    return d;
}

// ---------------------------------------------------------------------------
__global__ void init_keys() {
    int i = blockIdx.x * blockDim.x + threadIdx.x;
    if (i < N_THR) g_thr_keys[i] = 0u;   // key 0 == very negative float
}

// ---------------------------------------------------------------------------
// Conv 3x3, stride 1, pad 1, via packed f32x2 FMA: each thread computes a
// 2-tall pixel column; the row pair is one f32x2 accumulator, weights are
// pre-duplicated {w,w} in smem. Per-component rounding identical to scalar
// FFMA, accumulation order identical to previous rounds -> thr bit-exact.
__global__ void __launch_bounds__(128, 3) conv_kernel(const float* __restrict__ x,
                                                      const float* __restrict__ Wt) {
    __shared__ float    xs[CIN][10][34];     // 32x8 tile + halo
    __shared__ float2   ws2[COUT][28];       // duplicated weights {w,w}
    __shared__ unsigned swm[COUT][4];        // per-warp max keys

    const int tb  = blockIdx.z;              // t*B + b
    const int t   = tb >> 5;
    const int tid = threadIdx.y * 32 + threadIdx.x;
    const int wid = threadIdx.y;             // 4 warps

    for (int idx = tid; idx < COUT * 27; idx += 128) {
        int co = idx / 27;
        int j  = idx - co * 27;
        float w = Wt[idx];
        ws2[co][j] = make_float2(w, w);
    }
    if (tid < COUT) ws2[tid][27] = make_float2(0.f, 0.f);

    const float* xb = x + tb * (CIN * SPAT);
    const int y0 = blockIdx.y * 8;
    const int x0 = blockIdx.x * 32;
    for (int idx = tid; idx < CIN * 340; idx += 128) {
        int ci  = idx / 340;
        int rem = idx - ci * 340;
        int yy  = rem / 34;
        int xx  = rem - yy * 34;
        int gy = y0 + yy - 1, gx = x0 + xx - 1;
        float v = 0.f;
        if ((unsigned)gy < 64u && (unsigned)gx < 64u) v = xb[ci * SPAT + gy * 64 + gx];
        xs[ci][yy][xx] = v;
    }
    __syncthreads();

    const int px = threadIdx.x;
    const int py = threadIdx.y;              // rows 2py, 2py+1 of the 8-row tile
    // scalars rows 2py..2py+3, packed into row pairs rr=0..2
    unsigned long long rp[CIN][3][3];
#pragma unroll
    for (int ci = 0; ci < CIN; ci++) {
        float s[4][3];
#pragma unroll
        for (int rr = 0; rr < 4; rr++)
#pragma unroll
            for (int kx = 0; kx < 3; kx++)
                s[rr][kx] = xs[ci][2 * py + rr][px + kx];
#pragma unroll
        for (int rr = 0; rr < 3; rr++)
#pragma unroll
            for (int kx = 0; kx < 3; kx++)
                rp[ci][rr][kx] = pk2(s[rr][kx], s[rr + 1][kx]);
    }

    float* out = g_i + tb * (COUT * SPAT) + (y0 + 2 * py) * 64 + x0 + px;

#pragma unroll 1
    for (int co = 0; co < COUT; co++) {
        unsigned long long wl2[28];
        const ulonglong2* wv = (const ulonglong2*)ws2[co];
#pragma unroll
        for (int q = 0; q < 14; q++) {
            ulonglong2 p = wv[q];
            wl2[2 * q] = p.x; wl2[2 * q + 1] = p.y;
        }

        unsigned long long A0 = 0ull, A1 = 0ull, A2 = 0ull;
#pragma unroll
        for (int ky = 0; ky < 3; ky++)
#pragma unroll
            for (int kx = 0; kx < 3; kx++) {
                const int j = ky * 3 + kx;
                A0 = fma2(rp[0][ky][kx], wl2[j],      A0);
                A1 = fma2(rp[1][ky][kx], wl2[j + 9],  A1);
                A2 = fma2(rp[2][ky][kx], wl2[j + 18], A2);
            }
        unsigned long long S = add2(add2(A0, A1), A2);   // (a0+a1)+a2 per row
        float v0, v1;
        upk2(S, v0, v1);
        out[co * SPAT]      = v0;
        out[co * SPAT + 64] = v1;

        float mx = fmaxf(v0, v1);
        unsigned u   = __float_as_uint(mx);
        unsigned key = ((int)u < 0) ? ~u : (u | 0x80000000u);   // order-preserving
        key = __reduce_max_sync(0xffffffffu, key);
        if (px == 0) swm[co][wid] = key;
    }
    __syncthreads();
    if (tid < COUT) {
        unsigned m = swm[tid][0];
        m = max(m, swm[tid][1]); m = max(m, swm[tid][2]); m = max(m, swm[tid][3]);
        atomicMax(&g_thr_keys[t * COUT + tid], m);
    }
}

// ---------------------------------------------------------------------------
__global__ void finalize_thr() {
    int i = blockIdx.x * blockDim.x + threadIdx.x;
    if (i < N_THR) {
        unsigned k = g_thr_keys[i];
        unsigned u = (k & 0x80000000u) ? (k & 0x7FFFFFFFu) : ~k;
        float thr  = __uint_as_float(u) + 1e-4f;
        // zscale = 8*log2(e)/thr : sigmoid arg in exp2 domain
        float zs   = 11.541560f / thr;
        g_thrv[i]  = make_float4(thr, INH * thr, zs, 0.f);
    }
}

// ---------------------------------------------------------------------------
// LIF + ASF + WTA + inhibition (R5 structure) with FAST SIGMOID:
//   sigmoid((cur-0.4thr)*8/thr) = 1/(1+exp2(3.2*log2e - cur*(8*log2e/thr)))
//   -> FMAX + FFMA + MUFU.EX2 + FADD + MUFU.RCP + FMUL  (6 inst vs ~20)
#define KC 4.6166243f   /* 3.2 * log2(e) */
__global__ void __launch_bounds__(1024, 2) lif_kernel(float* __restrict__ out) {
    __shared__ float  smi[2][COUT][33];  // i tiles, [channel][pixel]
    __shared__ int    swz[2][32];        // winner code per pixel
    __shared__ float4 sthr[N_THR];       // cached thresholds

    const int tx  = threadIdx.x;         // lane
    const int ty  = threadIdx.y;         // warp
    const int tid = ty * 32 + tx;
    const int b   = blockIdx.x >> 7;     // 128 blocks per batch image
    const int spb = (blockIdx.x & 127) * 32;

    for (int i = tid; i < N_THR; i += 1024) sthr[i] = g_thrv[i];

    const int tstride = B_SZ * COUT * SPAT;            // elements per timestep
    const int row0    = (b * COUT + ty) * SPAT + spb + tx;
    const int row1    = row0 + 32 * SPAT;

    float l0 = g_i[row0];                // prefetch t = 0
    float l1 = g_i[row1];

    float mem0 = 0.f, mem1 = 0.f;

#pragma unroll
    for (int t = 0; t < T_STEPS; t++) {
        const int bt = t & 1;

        smi[bt][ty][tx]      = l0;
        smi[bt][ty + 32][tx] = l1;
        __syncthreads();

        if (t + 1 < T_STEPS) {           // prefetch t+1, overlaps compute
            l0 = g_i[row0 + (t + 1) * tstride];
            l1 = g_i[row1 + (t + 1) * tstride];
        }

        const float  i0  = smi[bt][tx][ty];
        const float  i1  = smi[bt][tx + 32][ty];
        const float4 tv0 = sthr[t * COUT + tx];
        const float4 tv1 = sthr[t * COUT + tx + 32];

        // fast ASF
        float zn0 = fmaf(fmaxf(i0, 0.f), -tv0.z, KC);
        float zn1 = fmaf(fmaxf(i1, 0.f), -tv1.z, KC);
        float e0, e1, q0, q1;
        asm("ex2.approx.f32 %0, %1;" : "=f"(e0) : "f"(zn0));
        asm("ex2.approx.f32 %0, %1;" : "=f"(e1) : "f"(zn1));
        asm("rcp.approx.f32 %0, %1;" : "=f"(q0) : "f"(1.f + e0));
        asm("rcp.approx.f32 %0, %1;" : "=f"(q1) : "f"(1.f + e1));
        float asf0 = tv0.x * q0;
        float asf1 = tv1.x * q1;

        mem0 = fmaf(mem0, DECAY, asf0);
        mem1 = fmaf(mem1, DECAY, asf1);

        const int   s0i = mem0 > tv0.x ? 1 : 0;
        const int   s1i = mem1 > tv1.x ? 1 : 0;
        const float sc0 = s0i ? mem0 : 0.f;
        const float sc1 = s1i ? mem1 : 0.f;

        // per-lane candidate; lower channel wins ties (argmax-first semantics)
        float bs; int bi;
        if (sc0 >= sc1) { bs = sc0; bi = (tx << 1) | s0i; }
        else            { bs = sc1; bi = ((tx + 32) << 1) | s1i; }

        unsigned ub  = __float_as_uint(bs);
        unsigned key = ((int)ub < 0) ? ~ub : (ub | 0x80000000u);
        unsigned mk  = __reduce_max_sync(0xffffffffu, key);
        unsigned cand = (key == mk) ? (unsigned)bi : 0x7fffffffu;
        const int wz = (int)__reduce_min_sync(0xffffffffu, cand);

        const int   wc  = wz >> 1;
        const float any = (float)(wz & 1);            // winner's spike -> any_sp

        const float sn0 = (wc == tx)      ? (float)s0i : 0.f;
        const float sn1 = (wc == tx + 32) ? (float)s1i : 0.f;

        mem0 = (sn0 > 0.f) ? 0.f : fmaf(-tv0.y, any, mem0);
        mem1 = (sn1 > 0.f) ? 0.f : fmaf(-tv1.y, any, mem1);

        if (tx == 0) swz[bt][ty] = wz;   // one word per pixel
        __syncthreads();

        const int wzp = swz[bt][tx];
        out[row0 + t * tstride] = (wzp == ((ty << 1) | 1))        ? 1.f : 0.f;
        out[row1 + t * tstride] = (wzp == (((ty + 32) << 1) | 1)) ? 1.f : 0.f;
    }
}

// ---------------------------------------------------------------------------
extern "C" void kernel_launch(void* const* d_in, const int* in_sizes, int n_in,
                              void* d_out, int out_size) {
    const float* x = (const float*)d_in[0];
    const float* W = (const float*)d_in[1];
    if (n_in >= 2 && in_sizes[0] == COUT * CIN * 9) {  // defensive order swap
        const float* tmp = x; x = W; W = tmp;
    }

    init_keys<<<1, N_THR>>>();

    dim3 cb(32, 4);
    dim3 cg(2, 8, T_STEPS * B_SZ);
    conv_kernel<<<cg, cb>>>(x, W);

    finalize_thr<<<1, N_THR>>>();

    lif_kernel<<<(B_SZ * SPAT) / 32, dim3(32, 32)>>>((float*)d_out);
}